// round 6
// baseline (speedup 1.0000x reference)
#include <cuda_runtime.h>
#include <cstdint>

// Problem constants
#define BB 4
#define SS 2048
#define EE 1024
#define HH 16
#define DD 64
static constexpr int BHSD = BB * HH * SS * DD;   // 8388608 elements per tensor

// Scratch: q, k, v, values  (4 * 32MB = 128MB device-global, no allocation)
__device__ float g_scratch[4LL * BHSD];

// ---------------------------------------------------------------------------
// helpers
// ---------------------------------------------------------------------------
__device__ __forceinline__ uint32_t f2tf(float f) {
    uint32_t u;
    asm("cvt.rna.tf32.f32 %0, %1;" : "=r"(u) : "f"(f));
    return u;
}

__device__ __forceinline__ void mma_tf32(float c[4], const uint32_t a[4], const uint32_t b[2]) {
    asm volatile(
        "mma.sync.aligned.m16n8k8.row.col.f32.tf32.tf32.f32 "
        "{%0,%1,%2,%3}, {%4,%5,%6,%7}, {%8,%9}, {%0,%1,%2,%3};\n"
        : "+f"(c[0]), "+f"(c[1]), "+f"(c[2]), "+f"(c[3])
        : "r"(a[0]), "r"(a[1]), "r"(a[2]), "r"(a[3]), "r"(b[0]), "r"(b[1]));
}

__device__ __forceinline__ void cp16(uint32_t dst_smem, const void* src) {
    asm volatile("cp.async.cg.shared.global [%0], [%1], 16;\n" :: "r"(dst_smem), "l"(src));
}
#define CP_COMMIT()  asm volatile("cp.async.commit_group;\n")
#define CP_WAIT(n)   asm volatile("cp.async.wait_group %0;\n" :: "n"(n))

// ---------------------------------------------------------------------------
// GEMM: C[M,N] = A[M,K] @ B[K,N], fp32 in, tf32 MMA, fp32 accum.
// Block tile 128x128, K-tile 32, 256 threads (8 warps, each 64x32).
// EPI==0: plain row-major store to C.
// EPI==1: scatter into q/k/v head-major buffers (C = base of q; k,v follow).
// ---------------------------------------------------------------------------
static constexpr int AS_TILE = 128 * 36;   // floats per A buffer
static constexpr int BS_TILE = 32 * 132;   // floats per B buffer
static constexpr int GEMM_SMEM_FLOATS = 2 * AS_TILE + 2 * BS_TILE;

__device__ __forceinline__ void qkv_store(float* __restrict__ base, int r, int c, float v) {
    // r in [0, B*S), c in [0, 3*E)
    int b = r >> 11;            // /2048
    int s = r & 2047;
    int h = c / 192;
    int rem = c - h * 192;
    int which = rem >> 6;       // 0=q,1=k,2=v
    int d = rem & 63;
    base[(size_t)which * BHSD + ((((size_t)(b * HH + h)) * SS + s) << 6) + d] = v;
}

__device__ __forceinline__ void gemm_load_tile(
    const float* __restrict__ A, const float* __restrict__ Bm,
    int N, int K, int bm, int bn, int kt, int buf, uint32_t smb, int tid)
{
    const int aR = tid >> 3, aC = (tid & 7) * 4;
    const int bR = tid >> 5, bC = (tid & 31) * 4;
    const float* Ag = A + (size_t)bm * K + kt * 32;
#pragma unroll
    for (int i = 0; i < 4; i++) {
        int r = aR + i * 32;
        cp16(smb + (uint32_t)(buf * AS_TILE + r * 36 + aC) * 4, Ag + (size_t)r * K + aC);
    }
    const float* Bg = Bm + (size_t)kt * 32 * N + bn;
#pragma unroll
    for (int i = 0; i < 4; i++) {
        int r = bR + i * 8;
        cp16(smb + (uint32_t)(2 * AS_TILE + buf * BS_TILE + r * 132 + bC) * 4,
             Bg + (size_t)r * N + bC);
    }
    CP_COMMIT();
}

template <int EPI>
__global__ __launch_bounds__(256, 2)
void gemm_tf32(const float* __restrict__ A, const float* __restrict__ Bm,
               int N, int K, float* __restrict__ C)
{
    extern __shared__ float sm[];
    const int tid = threadIdx.x;
    const int lane = tid & 31, warp = tid >> 5;
    const int wm = warp >> 2, wn = warp & 3;     // 2 x 4 warp grid
    const int g = lane >> 2, t = lane & 3;
    const int bm = blockIdx.y * 128, bn = blockIdx.x * 128;
    const uint32_t smb = (uint32_t)__cvta_generic_to_shared(sm);

    float acc[4][4][4];
#pragma unroll
    for (int mt = 0; mt < 4; mt++)
#pragma unroll
        for (int nt = 0; nt < 4; nt++)
#pragma unroll
            for (int i = 0; i < 4; i++) acc[mt][nt][i] = 0.0f;

    const int NT = K >> 5;
    gemm_load_tile(A, Bm, N, K, bm, bn, 0, 0, smb, tid);

    for (int kt = 0; kt < NT; kt++) {
        if (kt + 1 < NT) {
            gemm_load_tile(A, Bm, N, K, bm, bn, kt + 1, (kt + 1) & 1, smb, tid);
            CP_WAIT(1);
        } else {
            CP_WAIT(0);
        }
        __syncthreads();

        const float* Ab = sm + (kt & 1) * AS_TILE;
        const float* Bb = sm + 2 * AS_TILE + (kt & 1) * BS_TILE;
#pragma unroll
        for (int ks = 0; ks < 4; ks++) {
            uint32_t af[4][4];
#pragma unroll
            for (int mt = 0; mt < 4; mt++) {
                int row = wm * 64 + mt * 16 + g;
                int col = ks * 8 + t;
                af[mt][0] = f2tf(Ab[row * 36 + col]);
                af[mt][1] = f2tf(Ab[(row + 8) * 36 + col]);
                af[mt][2] = f2tf(Ab[row * 36 + col + 4]);
                af[mt][3] = f2tf(Ab[(row + 8) * 36 + col + 4]);
            }
            uint32_t bf[4][2];
#pragma unroll
            for (int nt = 0; nt < 4; nt++) {
                int col = wn * 32 + nt * 8 + g;
                int row = ks * 8 + t;
                bf[nt][0] = f2tf(Bb[row * 132 + col]);
                bf[nt][1] = f2tf(Bb[(row + 4) * 132 + col]);
            }
#pragma unroll
            for (int mt = 0; mt < 4; mt++)
#pragma unroll
                for (int nt = 0; nt < 4; nt++)
                    mma_tf32(acc[mt][nt], af[mt], bf[nt]);
        }
        __syncthreads();
    }

    // epilogue
#pragma unroll
    for (int mt = 0; mt < 4; mt++) {
#pragma unroll
        for (int nt = 0; nt < 4; nt++) {
            int r = bm + wm * 64 + mt * 16 + g;
            int c = bn + wn * 32 + nt * 8 + 2 * t;
            if (EPI == 0) {
                C[(size_t)r * N + c]           = acc[mt][nt][0];
                C[(size_t)r * N + c + 1]       = acc[mt][nt][1];
                C[(size_t)(r + 8) * N + c]     = acc[mt][nt][2];
                C[(size_t)(r + 8) * N + c + 1] = acc[mt][nt][3];
            } else {
                qkv_store(C, r,     c,     acc[mt][nt][0]);
                qkv_store(C, r,     c + 1, acc[mt][nt][1]);
                qkv_store(C, r + 8, c,     acc[mt][nt][2]);
                qkv_store(C, r + 8, c + 1, acc[mt][nt][3]);
            }
        }
    }
}

// ---------------------------------------------------------------------------
// Flash attention: one CTA per (b,h, 64-query block). 128 threads, 4 warps.
// Each warp owns 16 query rows (full 64-key width per KV iteration).
// K/V tiles are DOUBLE-BUFFERED: tile j+1 prefetched via cp.async while
// computing on tile j, so per-iteration L2 latency is hidden.
// Shared: Qs + Ks[2] + Vs[2] + Ps, each [64][68] floats (pitch 68).
// ---------------------------------------------------------------------------
static constexpr int ATT_PITCH = 68;
static constexpr int ATT_TILE = 64 * ATT_PITCH;
static constexpr int ATT_SMEM_FLOATS = 6 * ATT_TILE;   // Q, K0, K1, V0, V1, P

__device__ __forceinline__ void attn_load_kv(
    const float* __restrict__ Kg, const float* __restrict__ Vg,
    int j, int buf, uint32_t smb, int tid)
{
    int c4 = (tid & 15) * 4, r0 = tid >> 4;
    const float* Kt = Kg + (size_t)j * 64 * DD;
    const float* Vt = Vg + (size_t)j * 64 * DD;
    uint32_t kbase = (uint32_t)((1 + buf) * ATT_TILE) * 4;       // Ks[buf]
    uint32_t vbase = (uint32_t)((3 + buf) * ATT_TILE) * 4;       // Vs[buf]
#pragma unroll
    for (int i = 0; i < 8; i++) {
        int r = r0 + i * 8;
        cp16(smb + kbase + (uint32_t)(r * ATT_PITCH + c4) * 4, Kt + r * DD + c4);
    }
#pragma unroll
    for (int i = 0; i < 8; i++) {
        int r = r0 + i * 8;
        cp16(smb + vbase + (uint32_t)(r * ATT_PITCH + c4) * 4, Vt + r * DD + c4);
    }
    CP_COMMIT();
}

__global__ __launch_bounds__(128, 2)
void attn_kernel(const float* __restrict__ Q, const float* __restrict__ Kp,
                 const float* __restrict__ Vp, float* __restrict__ Out)
{
    extern __shared__ float sm[];
    float* Qs = sm;
    float* Ps = sm + 5 * ATT_TILE;

    const int tid = threadIdx.x, lane = tid & 31, warp = tid >> 5;
    const int g = lane >> 2, t = lane & 3;
    const int bh = blockIdx.y;             // b*H + h
    const int qb = blockIdx.x;             // query block (64 rows)
    const int b = bh >> 4, h = bh & 15;
    const float* Qg = Q + (size_t)bh * SS * DD + (size_t)qb * 64 * DD;
    const float* Kg = Kp + (size_t)bh * SS * DD;
    const float* Vg = Vp + (size_t)bh * SS * DD;
    const uint32_t smb = (uint32_t)__cvta_generic_to_shared(sm);
    const int qrow = warp * 16;

    // group 0: Q tile (64x64)
    {
        int c4 = (tid & 15) * 4, r0 = tid >> 4;
#pragma unroll
        for (int i = 0; i < 8; i++) {
            int r = r0 + i * 8;
            cp16(smb + (uint32_t)(r * ATT_PITCH + c4) * 4, Qg + r * DD + c4);
        }
        CP_COMMIT();
    }
    // group 1: KV tile 0
    attn_load_kv(Kg, Vg, 0, 0, smb, tid);

    float m0 = -3.0e38f, m1 = -3.0e38f, l0 = 0.0f, l1 = 0.0f;
    float o[8][4];
#pragma unroll
    for (int nt = 0; nt < 8; nt++)
#pragma unroll
        for (int i = 0; i < 4; i++) o[nt][i] = 0.0f;

    for (int j = 0; j < 32; j++) {
        // prefetch next KV tile into the other buffer, then wait for tile j
        if (j + 1 < 32) {
            attn_load_kv(Kg, Vg, j + 1, (j + 1) & 1, smb, tid);
            CP_WAIT(1);
        } else {
            CP_WAIT(0);
        }
        __syncthreads();   // tile j visible to all warps; prev compute done

        const float* Ks = sm + (1 + (j & 1)) * ATT_TILE;
        const float* Vs = sm + (3 + (j & 1)) * ATT_TILE;

        // S = Q @ K^T  (per warp: 16 rows x 64 keys, k-dim = 64)
        float s[8][4];
#pragma unroll
        for (int nt = 0; nt < 8; nt++)
#pragma unroll
            for (int i = 0; i < 4; i++) s[nt][i] = 0.0f;

#pragma unroll
        for (int ks = 0; ks < 8; ks++) {
            uint32_t af[4];
            int ro = qrow + g, co = ks * 8 + t;
            af[0] = f2tf(Qs[ro * ATT_PITCH + co]);
            af[1] = f2tf(Qs[(ro + 8) * ATT_PITCH + co]);
            af[2] = f2tf(Qs[ro * ATT_PITCH + co + 4]);
            af[3] = f2tf(Qs[(ro + 8) * ATT_PITCH + co + 4]);
#pragma unroll
            for (int nt = 0; nt < 8; nt++) {
                uint32_t bf[2];
                int kc = nt * 8 + g;                      // key index
                bf[0] = f2tf(Ks[kc * ATT_PITCH + co]);    // K[key][dh]
                bf[1] = f2tf(Ks[kc * ATT_PITCH + co + 4]);
                mma_tf32(s[nt], af, bf);
            }
        }

        // scale + online softmax (rows g, g+8 of this warp's 16)
        float rmax0 = -3.0e38f, rmax1 = -3.0e38f;
#pragma unroll
        for (int nt = 0; nt < 8; nt++) {
#pragma unroll
            for (int i = 0; i < 4; i++) s[nt][i] *= 0.125f;
            rmax0 = fmaxf(rmax0, fmaxf(s[nt][0], s[nt][1]));
            rmax1 = fmaxf(rmax1, fmaxf(s[nt][2], s[nt][3]));
        }
        rmax0 = fmaxf(rmax0, __shfl_xor_sync(0xffffffffu, rmax0, 1));
        rmax0 = fmaxf(rmax0, __shfl_xor_sync(0xffffffffu, rmax0, 2));
        rmax1 = fmaxf(rmax1, __shfl_xor_sync(0xffffffffu, rmax1, 1));
        rmax1 = fmaxf(rmax1, __shfl_xor_sync(0xffffffffu, rmax1, 2));

        float mn0 = fmaxf(m0, rmax0), mn1 = fmaxf(m1, rmax1);
        float a0 = __expf(m0 - mn0), a1 = __expf(m1 - mn1);
        m0 = mn0; m1 = mn1;

        float rs0 = 0.0f, rs1 = 0.0f;
#pragma unroll
        for (int nt = 0; nt < 8; nt++) {
            s[nt][0] = __expf(s[nt][0] - mn0);
            s[nt][1] = __expf(s[nt][1] - mn0);
            s[nt][2] = __expf(s[nt][2] - mn1);
            s[nt][3] = __expf(s[nt][3] - mn1);
            rs0 += s[nt][0] + s[nt][1];
            rs1 += s[nt][2] + s[nt][3];
        }
        rs0 += __shfl_xor_sync(0xffffffffu, rs0, 1);
        rs0 += __shfl_xor_sync(0xffffffffu, rs0, 2);
        rs1 += __shfl_xor_sync(0xffffffffu, rs1, 1);
        rs1 += __shfl_xor_sync(0xffffffffu, rs1, 2);
        l0 = l0 * a0 + rs0;
        l1 = l1 * a1 + rs1;

        // rescale O accumulators
#pragma unroll
        for (int nt = 0; nt < 8; nt++) {
            o[nt][0] *= a0; o[nt][1] *= a0;
            o[nt][2] *= a1; o[nt][3] *= a1;
        }

        // stage P to (warp-private rows of) shared
#pragma unroll
        for (int nt = 0; nt < 8; nt++) {
            int r = qrow + g, c = nt * 8 + 2 * t;
            Ps[r * ATT_PITCH + c]           = s[nt][0];
            Ps[r * ATT_PITCH + c + 1]       = s[nt][1];
            Ps[(r + 8) * ATT_PITCH + c]     = s[nt][2];
            Ps[(r + 8) * ATT_PITCH + c + 1] = s[nt][3];
        }
        __syncwarp();

        // O += P @ V   (k-dim = keys 64, n = dh 64)
#pragma unroll
        for (int ks = 0; ks < 8; ks++) {
            uint32_t af[4];
            int ro = qrow + g, co = ks * 8 + t;          // co = key index
            af[0] = f2tf(Ps[ro * ATT_PITCH + co]);
            af[1] = f2tf(Ps[(ro + 8) * ATT_PITCH + co]);
            af[2] = f2tf(Ps[ro * ATT_PITCH + co + 4]);
            af[3] = f2tf(Ps[(ro + 8) * ATT_PITCH + co + 4]);
#pragma unroll
            for (int nt = 0; nt < 8; nt++) {
                uint32_t bf[2];
                int vc = nt * 8 + g;                      // dh col
                bf[0] = f2tf(Vs[co * ATT_PITCH + vc]);    // V[key][dh]
                bf[1] = f2tf(Vs[(co + 4) * ATT_PITCH + vc]);
                mma_tf32(o[nt], af, bf);
            }
        }
        __syncthreads();   // all warps done with tile j before its buffer is refilled
    }

    // epilogue: normalize and write into values[b][s][h*64+d]
    float i0 = 1.0f / l0, i1 = 1.0f / l1;
#pragma unroll
    for (int nt = 0; nt < 8; nt++) {
        int srow = qb * 64 + qrow + g;
        int d = nt * 8 + 2 * t;
        size_t base0 = ((size_t)(b * SS + srow)) * EE + h * DD + d;
        size_t base1 = ((size_t)(b * SS + srow + 8)) * EE + h * DD + d;
        Out[base0]     = o[nt][0] * i0;
        Out[base0 + 1] = o[nt][1] * i0;
        Out[base1]     = o[nt][2] * i1;
        Out[base1 + 1] = o[nt][3] * i1;
    }
}

// ---------------------------------------------------------------------------
// launch
// ---------------------------------------------------------------------------
extern "C" void kernel_launch(void* const* d_in, const int* in_sizes, int n_in,
                              void* d_out, int out_size)
{
    const float* x    = (const float*)d_in[0];   // [4,2048,1024]
    const float* Wqkv = (const float*)d_in[1];   // [1024,3072]
    const float* Wout = (const float*)d_in[2];   // [1024,1024]
    float* out = (float*)d_out;                  // [4,2048,1024]

    float* scratch = nullptr;
    cudaGetSymbolAddress((void**)&scratch, g_scratch);
    float* q   = scratch;                 // qkv_store indexes k,v from this base
    float* k   = scratch + (size_t)BHSD;
    float* v   = scratch + (size_t)2 * BHSD;
    float* val = scratch + (size_t)3 * BHSD;
    (void)k; (void)v;

    const int smemG = GEMM_SMEM_FLOATS * 4;   // 70656 B
    const int smemA = ATT_SMEM_FLOATS * 4;    // 104448 B
    cudaFuncSetAttribute(gemm_tf32<1>, cudaFuncAttributeMaxDynamicSharedMemorySize, smemG);
    cudaFuncSetAttribute(gemm_tf32<0>, cudaFuncAttributeMaxDynamicSharedMemorySize, smemG);
    cudaFuncSetAttribute(attn_kernel,  cudaFuncAttributeMaxDynamicSharedMemorySize, smemA);

    // 1) QKV projection, scattered into head-major q/k/v
    gemm_tf32<1><<<dim3(3 * EE / 128, BB * SS / 128), 256, smemG>>>(x, Wqkv, 3 * EE, EE, q);
    // 2) flash attention -> values in [B,S,E] layout
    attn_kernel<<<dim3(SS / 64, BB * HH), 128, smemA>>>(
        scratch, scratch + (size_t)BHSD, scratch + (size_t)2 * BHSD, val);
    // 3) output projection
    gemm_tf32<0><<<dim3(EE / 128, BB * SS / 128), 256, smemG>>>(val, Wout, EE, EE, out);
}

// round 7
// speedup vs baseline: 1.1768x; 1.1768x over previous
#include <cuda_runtime.h>
#include <cstdint>

// Problem constants
#define BB 4
#define SS 2048
#define EE 1024
#define HH 16
#define DD 64
static constexpr int BHSD = BB * HH * SS * DD;   // 8388608 elements per tensor

// Scratch: q, k, v, values  (4 * 32MB = 128MB device-global, no allocation)
__device__ float g_scratch[4LL * BHSD];

// ---------------------------------------------------------------------------
// helpers
// ---------------------------------------------------------------------------
__device__ __forceinline__ uint32_t f2tf(float f) {
    uint32_t u;
    asm("cvt.rna.tf32.f32 %0, %1;" : "=r"(u) : "f"(f));
    return u;
}

__device__ __forceinline__ void mma_tf32(float c[4], const uint32_t a[4], const uint32_t b[2]) {
    asm volatile(
        "mma.sync.aligned.m16n8k8.row.col.f32.tf32.tf32.f32 "
        "{%0,%1,%2,%3}, {%4,%5,%6,%7}, {%8,%9}, {%0,%1,%2,%3};\n"
        : "+f"(c[0]), "+f"(c[1]), "+f"(c[2]), "+f"(c[3])
        : "r"(a[0]), "r"(a[1]), "r"(a[2]), "r"(a[3]), "r"(b[0]), "r"(b[1]));
}

__device__ __forceinline__ void cp16(uint32_t dst_smem, const void* src) {
    asm volatile("cp.async.cg.shared.global [%0], [%1], 16;\n" :: "r"(dst_smem), "l"(src));
}
#define CP_COMMIT()  asm volatile("cp.async.commit_group;\n")
#define CP_WAIT(n)   asm volatile("cp.async.wait_group %0;\n" :: "n"(n))

// ---------------------------------------------------------------------------
// GEMM: C[M,N] = A[M,K] @ B[K,N], fp32 in, tf32 MMA, fp32 accum.
// Block tile 128x128, K-tile 32, 128 threads (4 warps in 2x2, each 64x64).
// 128 B of shared reads per MMA (A and B fragments reused 8x / 4x).
// EPI==0: plain row-major store to C.
// EPI==1: scatter into q/k/v head-major buffers, PRE-ROUNDED to tf32.
// ---------------------------------------------------------------------------
static constexpr int AS_TILE = 128 * 36;   // floats per A buffer
static constexpr int BS_TILE = 32 * 132;   // floats per B buffer
static constexpr int GEMM_SMEM_FLOATS = 2 * AS_TILE + 2 * BS_TILE;

__device__ __forceinline__ void qkv_store(float* __restrict__ base, int r, int c, float v) {
    // r in [0, B*S), c in [0, 3*E).  Stored tf32-rounded (same bits the MMA
    // would consume), so attention can use raw loads with no cvt.
    int b = r >> 11;            // /2048
    int s = r & 2047;
    int h = c / 192;
    int rem = c - h * 192;
    int which = rem >> 6;       // 0=q,1=k,2=v
    int d = rem & 63;
    base[(size_t)which * BHSD + ((((size_t)(b * HH + h)) * SS + s) << 6) + d] =
        __uint_as_float(f2tf(v));
}

__device__ __forceinline__ void gemm_load_tile(
    const float* __restrict__ A, const float* __restrict__ Bm,
    int N, int K, int bm, int bn, int kt, int buf, uint32_t smb, int tid)
{
    const int aR = tid >> 3, aC = (tid & 7) * 4;
    const int bR = tid >> 5, bC = (tid & 31) * 4;
    const float* Ag = A + (size_t)bm * K + kt * 32;
#pragma unroll
    for (int i = 0; i < 8; i++) {
        int r = aR + i * 16;
        cp16(smb + (uint32_t)(buf * AS_TILE + r * 36 + aC) * 4, Ag + (size_t)r * K + aC);
    }
    const float* Bg = Bm + (size_t)kt * 32 * N + bn;
#pragma unroll
    for (int i = 0; i < 8; i++) {
        int r = bR + i * 4;
        cp16(smb + (uint32_t)(2 * AS_TILE + buf * BS_TILE + r * 132 + bC) * 4,
             Bg + (size_t)r * N + bC);
    }
    CP_COMMIT();
}

template <int EPI>
__global__ __launch_bounds__(128, 2)
void gemm_tf32(const float* __restrict__ A, const float* __restrict__ Bm,
               int N, int K, float* __restrict__ C)
{
    extern __shared__ float sm[];
    const int tid = threadIdx.x;
    const int lane = tid & 31, warp = tid >> 5;
    const int wm = warp >> 1, wn = warp & 1;     // 2 x 2 warp grid, 64x64 each
    const int g = lane >> 2, t = lane & 3;
    const int bm = blockIdx.y * 128, bn = blockIdx.x * 128;
    const uint32_t smb = (uint32_t)__cvta_generic_to_shared(sm);

    float acc[4][8][4];
#pragma unroll
    for (int mt = 0; mt < 4; mt++)
#pragma unroll
        for (int nt = 0; nt < 8; nt++)
#pragma unroll
            for (int i = 0; i < 4; i++) acc[mt][nt][i] = 0.0f;

    const int NT = K >> 5;
    gemm_load_tile(A, Bm, N, K, bm, bn, 0, 0, smb, tid);

    for (int kt = 0; kt < NT; kt++) {
        if (kt + 1 < NT) {
            gemm_load_tile(A, Bm, N, K, bm, bn, kt + 1, (kt + 1) & 1, smb, tid);
            CP_WAIT(1);
        } else {
            CP_WAIT(0);
        }
        __syncthreads();

        const float* Ab = sm + (kt & 1) * AS_TILE;
        const float* Bb = sm + 2 * AS_TILE + (kt & 1) * BS_TILE;
#pragma unroll
        for (int ks = 0; ks < 4; ks++) {
            uint32_t af[4][4];
#pragma unroll
            for (int mt = 0; mt < 4; mt++) {
                int row = wm * 64 + mt * 16 + g;
                int col = ks * 8 + t;
                af[mt][0] = f2tf(Ab[row * 36 + col]);
                af[mt][1] = f2tf(Ab[(row + 8) * 36 + col]);
                af[mt][2] = f2tf(Ab[row * 36 + col + 4]);
                af[mt][3] = f2tf(Ab[(row + 8) * 36 + col + 4]);
            }
            uint32_t bf[8][2];
#pragma unroll
            for (int nt = 0; nt < 8; nt++) {
                int col = wn * 64 + nt * 8 + g;
                int row = ks * 8 + t;
                bf[nt][0] = f2tf(Bb[row * 132 + col]);
                bf[nt][1] = f2tf(Bb[(row + 4) * 132 + col]);
            }
#pragma unroll
            for (int mt = 0; mt < 4; mt++)
#pragma unroll
                for (int nt = 0; nt < 8; nt++)
                    mma_tf32(acc[mt][nt], af[mt], bf[nt]);
        }
        __syncthreads();
    }

    // epilogue
#pragma unroll
    for (int mt = 0; mt < 4; mt++) {
#pragma unroll
        for (int nt = 0; nt < 8; nt++) {
            int r = bm + wm * 64 + mt * 16 + g;
            int c = bn + wn * 64 + nt * 8 + 2 * t;
            if (EPI == 0) {
                C[(size_t)r * N + c]           = acc[mt][nt][0];
                C[(size_t)r * N + c + 1]       = acc[mt][nt][1];
                C[(size_t)(r + 8) * N + c]     = acc[mt][nt][2];
                C[(size_t)(r + 8) * N + c + 1] = acc[mt][nt][3];
            } else {
                qkv_store(C, r,     c,     acc[mt][nt][0]);
                qkv_store(C, r,     c + 1, acc[mt][nt][1]);
                qkv_store(C, r + 8, c,     acc[mt][nt][2]);
                qkv_store(C, r + 8, c + 1, acc[mt][nt][3]);
            }
        }
    }
}

// ---------------------------------------------------------------------------
// Flash attention: one CTA per (b,h, 128-query block). 128 threads, 4 warps.
// Each warp owns 32 query rows (mt=2) x full 64-key width -> K/V fragments
// reused 2x. Q fragments are preloaded into registers ONCE (A traffic = 0 in
// the QK loop). Q/K/V arrive pre-rounded to tf32 -> raw-bit MMA operands.
// Shared: Qs[128] + Ks[64] + Vs[64] + Ps[128], pitch 68 floats.
// ---------------------------------------------------------------------------
static constexpr int AP = 68;
static constexpr int Q_OFF = 0;              // 128 rows
static constexpr int K_OFF = 128 * AP;       // 64 rows
static constexpr int V_OFF = K_OFF + 64 * AP;
static constexpr int P_OFF = V_OFF + 64 * AP;  // 128 rows
static constexpr int ATT_SMEM_FLOATS = P_OFF + 128 * AP;   // 384*68 = 26112

__device__ __forceinline__ void attn_load_kv(
    const float* __restrict__ Kg, const float* __restrict__ Vg,
    int j, uint32_t smb, int tid)
{
    int c4 = (tid & 15) * 4, r0 = tid >> 4;
    const float* Kt = Kg + (size_t)j * 64 * DD;
    const float* Vt = Vg + (size_t)j * 64 * DD;
#pragma unroll
    for (int i = 0; i < 4; i++) {
        int r = r0 + i * 8;
        cp16(smb + (uint32_t)(K_OFF + r * AP + c4) * 4, Kt + r * DD + c4);
        cp16(smb + (uint32_t)(V_OFF + r * AP + c4) * 4, Vt + r * DD + c4);
        cp16(smb + (uint32_t)(K_OFF + (r + 32) * AP + c4) * 4, Kt + (r + 32) * DD + c4);
        cp16(smb + (uint32_t)(V_OFF + (r + 32) * AP + c4) * 4, Vt + (r + 32) * DD + c4);
    }
    CP_COMMIT();
}

__global__ __launch_bounds__(128, 2)
void attn_kernel(const float* __restrict__ Q, const float* __restrict__ Kp,
                 const float* __restrict__ Vp, float* __restrict__ Out)
{
    extern __shared__ float sm[];
    float* Qs = sm + Q_OFF;
    float* Ks = sm + K_OFF;
    float* Vs = sm + V_OFF;
    float* Ps = sm + P_OFF;

    const int tid = threadIdx.x, lane = tid & 31, warp = tid >> 5;
    const int g = lane >> 2, t = lane & 3;
    const int bh = blockIdx.y;             // b*H + h
    const int qb = blockIdx.x;             // query block (128 rows)
    const int b = bh >> 4, h = bh & 15;
    const float* Qg = Q + (size_t)bh * SS * DD + (size_t)qb * 128 * DD;
    const float* Kg = Kp + (size_t)bh * SS * DD;
    const float* Vg = Vp + (size_t)bh * SS * DD;
    const uint32_t smb = (uint32_t)__cvta_generic_to_shared(sm);
    const int wr = warp * 32;              // warp's first query row

    // Q tile (128x64) + first KV tile
    {
        int c4 = (tid & 15) * 4, r0 = tid >> 4;
#pragma unroll
        for (int i = 0; i < 16; i++) {
            int r = r0 + i * 8;
            cp16(smb + (uint32_t)(Q_OFF + r * AP + c4) * 4, Qg + r * DD + c4);
        }
        CP_COMMIT();
    }
    attn_load_kv(Kg, Vg, 0, smb, tid);
    CP_WAIT(0);
    __syncthreads();

    // preload Q fragments (values already tf32-rounded -> raw bits)
    uint32_t qf[8][2][4];
#pragma unroll
    for (int ks = 0; ks < 8; ks++) {
#pragma unroll
        for (int mt = 0; mt < 2; mt++) {
            int ro = wr + mt * 16 + g, co = ks * 8 + t;
            qf[ks][mt][0] = __float_as_uint(Qs[ro * AP + co]);
            qf[ks][mt][1] = __float_as_uint(Qs[(ro + 8) * AP + co]);
            qf[ks][mt][2] = __float_as_uint(Qs[ro * AP + co + 4]);
            qf[ks][mt][3] = __float_as_uint(Qs[(ro + 8) * AP + co + 4]);
        }
    }

    float mx[2][2], lx[2][2];
#pragma unroll
    for (int mt = 0; mt < 2; mt++) { mx[mt][0] = mx[mt][1] = -3.0e38f; lx[mt][0] = lx[mt][1] = 0.0f; }
    float o[2][8][4];
#pragma unroll
    for (int mt = 0; mt < 2; mt++)
#pragma unroll
        for (int nt = 0; nt < 8; nt++)
#pragma unroll
            for (int i = 0; i < 4; i++) o[mt][nt][i] = 0.0f;

    for (int j = 0; j < 32; j++) {
        // S = Q @ K^T  (per warp: 32 rows x 64 keys)
        float s[2][8][4];
#pragma unroll
        for (int mt = 0; mt < 2; mt++)
#pragma unroll
            for (int nt = 0; nt < 8; nt++)
#pragma unroll
                for (int i = 0; i < 4; i++) s[mt][nt][i] = 0.0f;

#pragma unroll
        for (int ks = 0; ks < 8; ks++) {
            int co = ks * 8 + t;
#pragma unroll
            for (int nt = 0; nt < 8; nt++) {
                uint32_t bf[2];
                int kc = nt * 8 + g;                                  // key index
                bf[0] = __float_as_uint(Ks[kc * AP + co]);            // pre-rounded
                bf[1] = __float_as_uint(Ks[kc * AP + co + 4]);
                mma_tf32(s[0][nt], qf[ks][0], bf);
                mma_tf32(s[1][nt], qf[ks][1], bf);
            }
        }

        // scale + online softmax + stage P (per mt block of 16 rows)
#pragma unroll
        for (int mt = 0; mt < 2; mt++) {
            float rmax0 = -3.0e38f, rmax1 = -3.0e38f;
#pragma unroll
            for (int nt = 0; nt < 8; nt++) {
#pragma unroll
                for (int i = 0; i < 4; i++) s[mt][nt][i] *= 0.125f;
                rmax0 = fmaxf(rmax0, fmaxf(s[mt][nt][0], s[mt][nt][1]));
                rmax1 = fmaxf(rmax1, fmaxf(s[mt][nt][2], s[mt][nt][3]));
            }
            rmax0 = fmaxf(rmax0, __shfl_xor_sync(0xffffffffu, rmax0, 1));
            rmax0 = fmaxf(rmax0, __shfl_xor_sync(0xffffffffu, rmax0, 2));
            rmax1 = fmaxf(rmax1, __shfl_xor_sync(0xffffffffu, rmax1, 1));
            rmax1 = fmaxf(rmax1, __shfl_xor_sync(0xffffffffu, rmax1, 2));

            float mn0 = fmaxf(mx[mt][0], rmax0), mn1 = fmaxf(mx[mt][1], rmax1);
            float a0 = __expf(mx[mt][0] - mn0), a1 = __expf(mx[mt][1] - mn1);
            mx[mt][0] = mn0; mx[mt][1] = mn1;

            float rs0 = 0.0f, rs1 = 0.0f;
#pragma unroll
            for (int nt = 0; nt < 8; nt++) {
                s[mt][nt][0] = __expf(s[mt][nt][0] - mn0);
                s[mt][nt][1] = __expf(s[mt][nt][1] - mn0);
                s[mt][nt][2] = __expf(s[mt][nt][2] - mn1);
                s[mt][nt][3] = __expf(s[mt][nt][3] - mn1);
                rs0 += s[mt][nt][0] + s[mt][nt][1];
                rs1 += s[mt][nt][2] + s[mt][nt][3];
            }
            rs0 += __shfl_xor_sync(0xffffffffu, rs0, 1);
            rs0 += __shfl_xor_sync(0xffffffffu, rs0, 2);
            rs1 += __shfl_xor_sync(0xffffffffu, rs1, 1);
            rs1 += __shfl_xor_sync(0xffffffffu, rs1, 2);
            lx[mt][0] = lx[mt][0] * a0 + rs0;
            lx[mt][1] = lx[mt][1] * a1 + rs1;

#pragma unroll
            for (int nt = 0; nt < 8; nt++) {
                o[mt][nt][0] *= a0; o[mt][nt][1] *= a0;
                o[mt][nt][2] *= a1; o[mt][nt][3] *= a1;
            }

            // stage P rows (warp-private region of Ps)
#pragma unroll
            for (int nt = 0; nt < 8; nt++) {
                int r = wr + mt * 16 + g, c = nt * 8 + 2 * t;
                *(float2*)&Ps[r * AP + c]       = make_float2(s[mt][nt][0], s[mt][nt][1]);
                *(float2*)&Ps[(r + 8) * AP + c] = make_float2(s[mt][nt][2], s[mt][nt][3]);
            }
        }
        __syncwarp();

        // O += P @ V   (k-dim = 64 keys, n = 64 dh)
#pragma unroll
        for (int ks = 0; ks < 8; ks++) {
            int co = ks * 8 + t;                                      // key index
            uint32_t af[2][4];
#pragma unroll
            for (int mt = 0; mt < 2; mt++) {
                int ro = wr + mt * 16 + g;
                af[mt][0] = f2tf(Ps[ro * AP + co]);
                af[mt][1] = f2tf(Ps[(ro + 8) * AP + co]);
                af[mt][2] = f2tf(Ps[ro * AP + co + 4]);
                af[mt][3] = f2tf(Ps[(ro + 8) * AP + co + 4]);
            }
#pragma unroll
            for (int nt = 0; nt < 8; nt++) {
                uint32_t bf[2];
                int vc = nt * 8 + g;                                  // dh col
                bf[0] = __float_as_uint(Vs[co * AP + vc]);            // pre-rounded
                bf[1] = __float_as_uint(Vs[(co + 4) * AP + vc]);
                mma_tf32(o[0][nt], af[0], bf);
                mma_tf32(o[1][nt], af[1], bf);
            }
        }

        // load next KV tile (single buffer; all warps must be done reading)
        if (j + 1 < 32) {
            __syncthreads();
            attn_load_kv(Kg, Vg, j + 1, smb, tid);
            CP_WAIT(0);
            __syncthreads();
        }
    }

    // epilogue: normalize and write into values[b][s][h*64+d]
#pragma unroll
    for (int mt = 0; mt < 2; mt++) {
        float i0 = 1.0f / lx[mt][0], i1 = 1.0f / lx[mt][1];
#pragma unroll
        for (int nt = 0; nt < 8; nt++) {
            int srow = qb * 128 + wr + mt * 16 + g;
            int d = nt * 8 + 2 * t;
            size_t base0 = ((size_t)(b * SS + srow)) * EE + h * DD + d;
            size_t base1 = ((size_t)(b * SS + srow + 8)) * EE + h * DD + d;
            Out[base0]     = o[mt][nt][0] * i0;
            Out[base0 + 1] = o[mt][nt][1] * i0;
            Out[base1]     = o[mt][nt][2] * i1;
            Out[base1 + 1] = o[mt][nt][3] * i1;
        }
    }
}

// ---------------------------------------------------------------------------
// launch
// ---------------------------------------------------------------------------
extern "C" void kernel_launch(void* const* d_in, const int* in_sizes, int n_in,
                              void* d_out, int out_size)
{
    const float* x    = (const float*)d_in[0];   // [4,2048,1024]
    const float* Wqkv = (const float*)d_in[1];   // [1024,3072]
    const float* Wout = (const float*)d_in[2];   // [1024,1024]
    float* out = (float*)d_out;                  // [4,2048,1024]

    float* scratch = nullptr;
    cudaGetSymbolAddress((void**)&scratch, g_scratch);
    float* q   = scratch;                 // qkv_store indexes k,v from this base
    float* val = scratch + (size_t)3 * BHSD;

    const int smemG = GEMM_SMEM_FLOATS * 4;   // 70656 B
    const int smemA = ATT_SMEM_FLOATS * 4;    // 104448 B
    cudaFuncSetAttribute(gemm_tf32<1>, cudaFuncAttributeMaxDynamicSharedMemorySize, smemG);
    cudaFuncSetAttribute(gemm_tf32<0>, cudaFuncAttributeMaxDynamicSharedMemorySize, smemG);
    cudaFuncSetAttribute(attn_kernel,  cudaFuncAttributeMaxDynamicSharedMemorySize, smemA);

    // 1) QKV projection, scattered (tf32-rounded) into head-major q/k/v
    gemm_tf32<1><<<dim3(3 * EE / 128, BB * SS / 128), 128, smemG>>>(x, Wqkv, 3 * EE, EE, q);
    // 2) flash attention -> values in [B,S,E] layout
    attn_kernel<<<dim3(SS / 128, BB * HH), 128, smemA>>>(
        scratch, scratch + (size_t)BHSD, scratch + (size_t)2 * BHSD, val);
    // 3) output projection
    gemm_tf32<0><<<dim3(EE / 128, BB * SS / 128), 128, smemG>>>(val, Wout, EE, EE, out);
}